// round 15
// baseline (speedup 1.0000x reference)
#include <cuda_runtime.h>
#include <math.h>
#include <stdint.h>

#define NB 4
#define CIN 256
#define CO 256
#define HDIM 56
#define WDIM 56
#define HW 3136
#define NCOL 12544     // NB*HW
#define NHEAD 2
#define HD 128
#define EPS 1e-5f
#define SEH 16
#define NPAN 98        // NCOL/128
#define CHUNKW 2048    // u32 per 128x16 chunk image

// attention dynamic smem layout (floats)
#define KV_STRIDE 132
#define KV_OFF   0                               // K' [72][132]
#define VB_OFF   (72 * KV_STRIDE)                // V  [64][132]  -> 9504
#define QB_OFF   (VB_OFF + 64 * KV_STRIDE)       // Q/attnw [16][132] -> 17952
#define AW_STRIDE 68
#define SS_OFF   (QB_OFF + 16 * KV_STRIDE)       // scores [16][76] -> 20064
#define SS_STRIDE 76
#define SMEM_ATTN ((SS_OFF + 16 * SS_STRIDE) * 4)   // 85120 bytes

// ---------------- scratch (device globals, no allocation) ----------------
__device__ uint32_t g_Wp [4 * 2 * 16 * CHUNKW];   // weight A-panels (tf32 frag layout)
__device__ uint32_t g_xtp[NPAN * 16 * CHUNKW];    // x B-panels
__device__ uint32_t g_y1p[NPAN * 16 * CHUNKW];    // y1 B-panels
__device__ uint32_t g_y2p[NPAN * 16 * CHUNKW];    // y2 B-panels
__device__ float g_qt[NCOL * CO];   // [n][c]  (tf32-rounded)
__device__ float g_kt[NCOL * CO];
__device__ float g_vt[NCOL * CO];
__device__ float g_s [NB * SEH * HW]; // channel-major [b][j][hw]
__device__ float g_p [NB * SEH];

// ---------------- helpers ----------------
__device__ __forceinline__ uint32_t f2tf32(float f) {
    uint32_t u;
    asm("cvt.rna.tf32.f32 %0, %1;" : "=r"(u) : "f"(f));
    return u;
}
__device__ __forceinline__ float f2tf32f(float f) {
    return __uint_as_float(f2tf32(f));
}
__device__ __forceinline__ void cpasync16(uint32_t smem, const void* g) {
    asm volatile("cp.async.cg.shared.global [%0], [%1], 16;" :: "r"(smem), "l"(g));
}
__device__ __forceinline__ uint32_t smem_u32x(const void* p) {
    uint32_t a;
    asm("{ .reg .u64 t; cvta.to.shared.u64 t, %1; cvt.u32.u64 %0, t; }" : "=r"(a) : "l"(p));
    return a;
}
__device__ __forceinline__ void mma_tf32(float* d, const uint32_t* a, const uint32_t* b) {
    asm volatile(
        "mma.sync.aligned.m16n8k8.row.col.f32.tf32.tf32.f32 "
        "{%0,%1,%2,%3}, {%4,%5,%6,%7}, {%8,%9}, {%0,%1,%2,%3};"
        : "+f"(d[0]), "+f"(d[1]), "+f"(d[2]), "+f"(d[3])
        : "r"(a[0]), "r"(a[1]), "r"(a[2]), "r"(a[3]), "r"(b[0]), "r"(b[1]));
}

// A-image u32 offset within one 128x16 chunk (m rows x k cols)
__device__ __forceinline__ int a_off(int m, int k) {
    int ks = k >> 3, mtile = m >> 4, mi = m & 15;
    int lane = (mi & 7) * 4 + (k & 3);
    int slot = (mi >> 3) + 2 * ((k >> 2) & 1);
    int I = (ks * 8 + mtile) * 32 + lane;
    I ^= (I >> 3) & 3;
    return I * 4 + slot;
}
// B-image u32 offset within one 128x16 chunk (n rows x k cols)
__device__ __forceinline__ int b_off(int n, int k) {
    int ks = k >> 3, ntile = n >> 3;
    int lane = (n & 7) * 4 + (k & 3);
    int slot = (k >> 2) & 1;
    int I = (ks * 16 + ntile) * 32 + lane;
    I ^= (I >> 4) & 3;
    return I * 2 + slot;
}

// ---------------- prep: weight repack + x transpose (merged) ----------------
// blocks [0,1024): repack 4 weight matrices -> A-panels (+ zero g_p in blk 0)
// blocks [1024,4160): transpose x -> B-panels
__global__ void prep_kernel(const float* __restrict__ x,
                            const float* __restrict__ Wq, const float* __restrict__ Wk,
                            const float* __restrict__ Wv, const float* __restrict__ Wa) {
    __shared__ float t[32][33];
    int tid = threadIdx.x;
    if (blockIdx.x < 1024) {
        if (blockIdx.x == 0 && tid < NB * SEH) g_p[tid] = 0.f;
        int v = blockIdx.x * 256 + tid;
        int mat = v >> 16;
        int rem = v & 65535;
        int o = rem >> 8, c = rem & 255;
        const float* W = (mat == 0) ? Wq : (mat == 1 ? Wk : (mat == 2 ? Wv : Wa));
        uint32_t u = f2tf32(W[o * 256 + c]);
        g_Wp[(((size_t)mat * 2 + (o >> 7)) * 16 + (c >> 4)) * CHUNKW + a_off(o & 127, c & 15)] = u;
    } else {
        int p = blockIdx.x - 1024;       // 3136 blocks = 4 * 8 * 98
        int b = p / 784;
        int r = p % 784;
        int c0 = (r / 98) * 32, p0 = (r % 98) * 32;
        int tx = tid & 31, ty = tid >> 5;
        const float* xb = x + ((size_t)b * CIN + c0) * HW + p0;
#pragma unroll
        for (int i = 0; i < 4; i++)
            t[ty * 4 + i][tx] = xb[(size_t)(ty * 4 + i) * HW + tx];
        __syncthreads();
        int c = c0 + tx;
#pragma unroll
        for (int i = 0; i < 4; i++) {
            int nglob = b * HW + p0 + ty * 4 + i;
            int ntile = nglob >> 7, nn = nglob & 127;
            g_xtp[((size_t)ntile * 16 + (c >> 4)) * CHUNKW + b_off(nn, c & 15)]
                = f2tf32(t[tx][ty * 4 + i]);
        }
    }
}

// ---------------- tensor-core tf32 GEMM, cp.async 3-stage, M128 x N128 -----
// mode 0: qkv (z selects matrix 0..2, B=g_xtp, out flat [n][c] tf32-rounded)
// mode 1: agg (matrix 3, B=g_y1p, out g_y2p panels with BN2, tf32-rounded)
__global__ __launch_bounds__(256, 2) void gemm_mma_kernel(
    const float* __restrict__ g2, const float* __restrict__ b2,
    const float* __restrict__ m2, const float* __restrict__ v2,
    int mode)
{
    __shared__ __align__(16) char smraw[49152];
    float* stg = (float*)smraw;

    int tid = threadIdx.x;
    int wid = tid >> 5, lane = tid & 31;
    int warpM = wid >> 2, warpN = wid & 3;
    int g = lane >> 2, t = lane & 3;

    int mat;
    const uint32_t* Bbase;
    float* outp = nullptr;
    if (mode == 0) {
        mat = blockIdx.z;
        Bbase = g_xtp;
        outp = (mat == 0) ? g_qt : (mat == 1 ? g_kt : g_vt);
    } else {
        mat = 3; Bbase = g_y1p;
    }
    int o0 = blockIdx.y * 128;
    int n0 = blockIdx.x * 128;

    const uint4* Apan = (const uint4*)&g_Wp[((size_t)mat * 2 + blockIdx.y) * 16 * CHUNKW];
    const uint4* Bpan = (const uint4*)&Bbase[(size_t)blockIdx.x * 16 * CHUNKW];
    uint32_t smb = smem_u32x(smraw);

    float acc[4][4][4];
#pragma unroll
    for (int i = 0; i < 4; i++)
#pragma unroll
        for (int j = 0; j < 4; j++)
#pragma unroll
            for (int s = 0; s < 4; s++) acc[i][j][s] = 0.f;

#define ISSUE(c, s) do { \
        uint32_t dst = smb + (s) * 16384; \
        const uint4* sa = Apan + (c) * 512; \
        const uint4* sb = Bpan + (c) * 512; \
        cpasync16(dst + tid * 16,                sa + tid); \
        cpasync16(dst + (tid + 256) * 16,        sa + tid + 256); \
        cpasync16(dst + 8192 + tid * 16,         sb + tid); \
        cpasync16(dst + 8192 + (tid + 256) * 16, sb + tid + 256); \
        asm volatile("cp.async.commit_group;"); \
    } while (0)

    ISSUE(0, 0);
    ISSUE(1, 1);

    for (int c = 0; c < 16; c++) {
        if (c < 15) asm volatile("cp.async.wait_group 1;");
        else        asm volatile("cp.async.wait_group 0;");
        __syncthreads();
        if (c + 2 < 16) ISSUE(c + 2, (c + 2) % 3);

        const uint4* Ab = (const uint4*)(smraw + (c % 3) * 16384);
        const uint2* Bb = (const uint2*)(smraw + (c % 3) * 16384 + 8192);
#pragma unroll
        for (int ks = 0; ks < 2; ks++) {
            uint32_t af[4][4], bf[4][2];
#pragma unroll
            for (int mt = 0; mt < 4; mt++) {
                int idx = (ks * 8 + warpM * 4 + mt) * 32 + lane;
                idx ^= (idx >> 3) & 3;
                uint4 v = Ab[idx];
                af[mt][0] = v.x; af[mt][1] = v.y; af[mt][2] = v.z; af[mt][3] = v.w;
            }
#pragma unroll
            for (int nt = 0; nt < 4; nt++) {
                int idx = (ks * 16 + warpN * 4 + nt) * 32 + lane;
                idx ^= (idx >> 4) & 3;
                uint2 v = Bb[idx];
                bf[nt][0] = v.x; bf[nt][1] = v.y;
            }
#pragma unroll
            for (int mt = 0; mt < 4; mt++)
#pragma unroll
                for (int nt = 0; nt < 4; nt++)
                    mma_tf32(acc[mt][nt], af[mt], bf[nt]);
        }
        __syncthreads();
    }
#undef ISSUE

    int h_of_warp = warpN >> 1;
    for (int h = 0; h < 2; h++) {
        __syncthreads();
        if (h_of_warp == h) {
#pragma unroll
            for (int mt = 0; mt < 4; mt++)
#pragma unroll
                for (int nt = 0; nt < 4; nt++)
#pragma unroll
                    for (int s = 0; s < 4; s++) {
                        int ol = warpM * 64 + mt * 16 + g + (s >> 1) * 8;
                        int nl = (warpN & 1) * 32 + nt * 8 + 2 * t + (s & 1);
                        stg[nl * 132 + ol] = acc[mt][nt][s];
                    }
        }
        __syncthreads();
#pragma unroll
        for (int i = 0; i < 8; i++) {
            int idx = tid + 256 * i;
            int nl = idx >> 5, o4 = idx & 31;
            float4 v = *(float4*)&stg[nl * 132 + o4 * 4];
            int nglob = n0 + h * 64 + nl;
            if (mode == 1) {
                int ob = o0 + o4 * 4;
                float4 gg = *(const float4*)&g2[ob];
                float4 bb = *(const float4*)&b2[ob];
                float4 mm = *(const float4*)&m2[ob];
                float4 vv = *(const float4*)&v2[ob];
                float s0 = gg.x * rsqrtf(vv.x + EPS);
                float s1 = gg.y * rsqrtf(vv.y + EPS);
                float s2 = gg.z * rsqrtf(vv.z + EPS);
                float s3 = gg.w * rsqrtf(vv.w + EPS);
                v.x = v.x * s0 + (bb.x - mm.x * s0);
                v.y = v.y * s1 + (bb.y - mm.y * s1);
                v.z = v.z * s2 + (bb.z - mm.z * s2);
                v.w = v.w * s3 + (bb.w - mm.w * s3);
                int pt = nglob >> 7, nn = nglob & 127;
                uint32_t* pb = &g_y2p[((size_t)pt * 16) * CHUNKW];
                const float* pv = &v.x;
#pragma unroll
                for (int j = 0; j < 4; j++) {
                    int ch = ob + j;
                    pb[(size_t)(ch >> 4) * CHUNKW + b_off(nn, ch & 15)] = f2tf32(pv[j]);
                }
            } else {
                v.x = f2tf32f(v.x); v.y = f2tf32f(v.y);
                v.z = f2tf32f(v.z); v.w = f2tf32f(v.w);
                *(float4*)&outp[(size_t)nglob * 256 + o0 + o4 * 4] = v;
            }
        }
    }
}

// ---------------- attention: tensor-core (mma.sync tf32) --------------------
// V prefetched via cp.async into its own buffer; waits only before AV mma.
__global__ void attn_kernel(const float* __restrict__ rel_h,
                            const float* __restrict__ rel_w,
                            const float* __restrict__ g1, const float* __restrict__ b1,
                            const float* __restrict__ m1, const float* __restrict__ v1) {
    extern __shared__ float sm[];
    float* kv = sm + KV_OFF;     // [72][132]  K' (halo + rel rows)
    float* vb = sm + VB_OFF;     // [64][132]  V
    float* qb = sm + QB_OFF;     // [16][132]  Q, later attnw[16][68]
    float* sS = sm + SS_OFF;     // [16][76]   scores, later scl[128]/bo[128]

    int tid = threadIdx.x, wid = tid >> 5, lane = tid & 31;
    int g = lane >> 2, t4 = lane & 3;
    int tile = blockIdx.x;
    int th = tile / 14, tw = tile % 14;
    int nh = blockIdx.y, b = blockIdx.z;
    int h0 = th * 4, w0 = tw * 4;
    const float* rel = nh ? rel_w : rel_h;

    // ---- prefetch V via cp.async (OOB -> zero STS) ----
    const float* vbase = g_vt + (size_t)b * HW * CO + nh * HD;
    uint32_t vb_s = smem_u32x(vb);
#pragma unroll
    for (int i = 0; i < 8; i++) {
        int f = tid + 256 * i;
        int pos = f >> 5, c4 = f & 31;
        int hh = h0 - 2 + (pos >> 3), ww = w0 - 2 + (pos & 7);
        uint32_t dst = vb_s + (pos * KV_STRIDE + c4 * 4) * 4;
        if ((unsigned)hh < HDIM && (unsigned)ww < WDIM)
            cpasync16(dst, &vbase[(size_t)(hh * WDIM + ww) * CO + c4 * 4]);
        else
            *(float4*)&vb[pos * KV_STRIDE + c4 * 4] = make_float4(0.f, 0.f, 0.f, 0.f);
    }
    asm volatile("cp.async.commit_group;");

    // ---- load Q (already tf32) ----
    const float* qbase = g_qt + (size_t)b * HW * CO + nh * HD;
#pragma unroll
    for (int i = 0; i < 2; i++) {
        int f = tid + 256 * i;
        int m = f >> 5, c4 = f & 31;
        int hw = (h0 + (m >> 2)) * WDIM + w0 + (m & 3);
        *(float4*)&qb[m * KV_STRIDE + c4 * 4] =
            *(const float4*)&qbase[(size_t)hw * CO + c4 * 4];
    }
    // ---- load K halo ----
    const float* kbase = g_kt + (size_t)b * HW * CO + nh * HD;
#pragma unroll
    for (int i = 0; i < 8; i++) {
        int f = tid + 256 * i;
        int pos = f >> 5, c4 = f & 31;
        int hh = h0 - 2 + (pos >> 3), ww = w0 - 2 + (pos & 7);
        float4 v = make_float4(0.f, 0.f, 0.f, 0.f);
        if ((unsigned)hh < HDIM && (unsigned)ww < WDIM)
            v = *(const float4*)&kbase[(size_t)(hh * WDIM + ww) * CO + c4 * 4];
        *(float4*)&kv[pos * KV_STRIDE + c4 * 4] = v;
    }
    // ---- rel rows 64..68, zeros 69..71 ----
    {
        int pos = 64 + (tid >> 5), c4 = tid & 31;
        float4 r = make_float4(0.f, 0.f, 0.f, 0.f);
        if (pos < 69) {
            int tp = pos - 64;
            r.x = f2tf32f(rel[(c4 * 4 + 0) * 5 + tp]);
            r.y = f2tf32f(rel[(c4 * 4 + 1) * 5 + tp]);
            r.z = f2tf32f(rel[(c4 * 4 + 2) * 5 + tp]);
            r.w = f2tf32f(rel[(c4 * 4 + 3) * 5 + tp]);
        }
        *(float4*)&kv[pos * KV_STRIDE + c4 * 4] = r;
    }
    __syncthreads();

    // ---- scores mma ----
    float accS0[4] = {0.f, 0.f, 0.f, 0.f};
    float accS1[4] = {0.f, 0.f, 0.f, 0.f};
#pragma unroll
    for (int ks = 0; ks < 16; ks++) {
        int kk = ks * 8 + t4;
        uint32_t a[4];
        a[0] = __float_as_uint(qb[g * KV_STRIDE + kk]);
        a[1] = __float_as_uint(qb[(g + 8) * KV_STRIDE + kk]);
        a[2] = __float_as_uint(qb[g * KV_STRIDE + kk + 4]);
        a[3] = __float_as_uint(qb[(g + 8) * KV_STRIDE + kk + 4]);
        uint32_t bb[2];
        bb[0] = __float_as_uint(kv[(wid * 8 + g) * KV_STRIDE + kk]);
        bb[1] = __float_as_uint(kv[(wid * 8 + g) * KV_STRIDE + kk + 4]);
        mma_tf32(accS0, a, bb);
        if (wid == 0) {
            uint32_t b2r[2];
            b2r[0] = __float_as_uint(kv[(64 + g) * KV_STRIDE + kk]);
            b2r[1] = __float_as_uint(kv[(64 + g) * KV_STRIDE + kk + 4]);
            mma_tf32(accS1, a, b2r);
        }
    }
#pragma unroll
    for (int s = 0; s < 4; s++) {
        int m = g + (s >> 1) * 8;
        sS[m * SS_STRIDE + wid * 8 + 2 * t4 + (s & 1)] = accS0[s];
        if (wid == 0) sS[m * SS_STRIDE + 64 + 2 * t4 + (s & 1)] = accS1[s];
    }
    __syncthreads();

    // ---- softmax ----
#pragma unroll
    for (int pp = 0; pp < 2; pp++) {
        int pi = wid * 2 + pp;
        int py = pi >> 2, px = pi & 3;
        float scv = -1e30f;
        int pos = 0;
        if (lane < 25) {
            int ki = lane / 5, kj = lane % 5;
            pos = (py + ki) * 8 + (px + kj);
            float bias = sS[pi * SS_STRIDE + 64 + (nh ? kj : ki)];
            scv = (sS[pi * SS_STRIDE + pos] + bias) * 0.08838834764831845f;
        }
        float mx = scv;
#pragma unroll
        for (int m = 16; m; m >>= 1) mx = fmaxf(mx, __shfl_xor_sync(0xffffffffu, mx, m));
        float e = (lane < 25) ? __expf(scv - mx) : 0.f;
        float ssum = e;
#pragma unroll
        for (int m = 16; m; m >>= 1) ssum += __shfl_xor_sync(0xffffffffu, ssum, m);
        float wv = e / ssum;
        float* aw = qb;
        aw[pi * AW_STRIDE + lane] = 0.f;
        aw[pi * AW_STRIDE + 32 + lane] = 0.f;
        if (lane < 25) aw[pi * AW_STRIDE + pos] = f2tf32f(wv);
    }
    asm volatile("cp.async.wait_group 0;" ::: "memory");
    __syncthreads();

    // ---- BN1 scale/bias into sS ----
    if (tid < 128) {
        int ch = nh * HD + tid;
        float scl = g1[ch] * rsqrtf(v1[ch] + EPS);
        sS[tid] = scl;
        sS[128 + tid] = b1[ch] - m1[ch] * scl;
    }

    // ---- AV mma (from prefetched vb) ----
    float accV0[4] = {0.f, 0.f, 0.f, 0.f};
    float accV1[4] = {0.f, 0.f, 0.f, 0.f};
#pragma unroll
    for (int ks = 0; ks < 8; ks++) {
        int kk = ks * 8 + t4;
        uint32_t a[4];
        a[0] = __float_as_uint(qb[g * AW_STRIDE + kk]);
        a[1] = __float_as_uint(qb[(g + 8) * AW_STRIDE + kk]);
        a[2] = __float_as_uint(qb[g * AW_STRIDE + kk + 4]);
        a[3] = __float_as_uint(qb[(g + 8) * AW_STRIDE + kk + 4]);
        uint32_t bb[2];
        int c0 = wid * 16 + g;
        bb[0] = __float_as_uint(vb[kk * KV_STRIDE + c0]);
        bb[1] = __float_as_uint(vb[(kk + 4) * KV_STRIDE + c0]);
        mma_tf32(accV0, a, bb);
        bb[0] = __float_as_uint(vb[kk * KV_STRIDE + c0 + 8]);
        bb[1] = __float_as_uint(vb[(kk + 4) * KV_STRIDE + c0 + 8]);
        mma_tf32(accV1, a, bb);
    }
    __syncthreads();

    // ---- epilogue: BN1 + relu -> g_y1p panels ----
#pragma unroll
    for (int j = 0; j < 2; j++) {
        const float* acc = j ? accV1 : accV0;
        int ntc = wid * 2 + j;
#pragma unroll
        for (int s = 0; s < 4; s++) {
            int m = g + (s >> 1) * 8;
            int c = ntc * 8 + 2 * t4 + (s & 1);
            int ch = nh * HD + c;
            int hw = (h0 + (m >> 2)) * WDIM + w0 + (m & 3);
            int nglob = b * HW + hw;
            float val = fmaxf(acc[s] * sS[c] + sS[128 + c], 0.f);
            g_y1p[((size_t)(nglob >> 7) * 16 + (ch >> 4)) * CHUNKW + b_off(nglob & 127, ch & 15)]
                = f2tf32(val);
        }
    }
}

// ---------------- SE stage 1: mma over y2 panels ----------------
__global__ __launch_bounds__(256) void se1_kernel(const float* __restrict__ Win,
                           const float* __restrict__ gin, const float* __restrict__ bin,
                           const float* __restrict__ min_, const float* __restrict__ vin) {
    __shared__ uint32_t Wf[4096];
    __shared__ float bnscl[SEH], bnbo[SEH];
    __shared__ float pool[2][SEH];
    int tid = threadIdx.x, wid = tid >> 5, lane = tid & 31;
    int g = lane >> 2, t4 = lane & 3;

#pragma unroll
    for (int it = 0; it < 16; it++) {
        int i = tid + 256 * it;
        int m = i >> 8, k = i & 255;
        int kc = k >> 4, ks = (k >> 3) & 1;
        int laneA = (m & 7) * 4 + (k & 3);
        int slot = (m >> 3) + 2 * ((k >> 2) & 1);
        Wf[((kc * 2 + ks) * 32 + laneA) * 4 + slot] = f2tf32(Win[m * 256 + k]);
    }
    if (tid < SEH) {
        float scl = gin[tid] * rsqrtf(vin[tid] + EPS);
        bnscl[tid] = scl;
        bnbo[tid] = bin[tid] - min_[tid] * scl;
        pool[0][tid] = 0.f;
        pool[1][tid] = 0.f;
    }
    __syncthreads();

    int panel = blockIdx.x;
    const uint32_t* Bpan = g_y2p + (size_t)panel * 16 * CHUNKW;

    float acc[2][4];
#pragma unroll
    for (int nt = 0; nt < 2; nt++)
#pragma unroll
        for (int s = 0; s < 4; s++) acc[nt][s] = 0.f;

#pragma unroll
    for (int kc = 0; kc < 16; kc++) {
#pragma unroll
        for (int ks = 0; ks < 2; ks++) {
            uint4 av = ((const uint4*)Wf)[(kc * 2 + ks) * 32 + lane];
            uint32_t a[4] = {av.x, av.y, av.z, av.w};
#pragma unroll
            for (int nt = 0; nt < 2; nt++) {
                int ntile = wid * 2 + nt;
                int idx = (ks * 16 + ntile) * 32 + lane;
                idx ^= (idx >> 4) & 3;
                uint2 bv = *(const uint2*)(Bpan + (size_t)kc * CHUNKW + idx * 2);
                uint32_t bb[2] = {bv.x, bv.y};
                mma_tf32(acc[nt], a, bb);
            }
        }
    }

    int b_first = (panel * 128) / HW;
#pragma unroll
    for (int nt = 0; nt < 2; nt++) {
        int ntile = wid * 2 + nt;
#pragma unroll
        for (int s = 0; s < 4; s++) {
            int j = g + (s >> 1) * 8;
            int pix = ntile * 8 + 2 * t4 + (s & 1);
            int nglob = panel * 128 + pix;
            int b = nglob / HW, hw = nglob % HW;
            float sv = fmaxf(acc[nt][s] * bnscl[j] + bnbo[j], 0.f);
            g_s[(size_t)b * SEH * HW + (size_t)j * HW + hw] = sv;
            atomicAdd(&pool[b - b_first][j], sv);
        }
    }
    __syncthreads();
    if (tid < 2 * SEH) {
        int bl = tid >> 4, j = tid & 15;
        int b = b_first + bl;
        if (b < NB) atomicAdd(&g_p[b * SEH + j], pool[bl][j]);
    }
}

// ---------------- SE stage 3 (gates computed inline from g_p) ----------------
__global__ void se3_kernel(const float* __restrict__ fc1, const float* __restrict__ fc2,
                           const float* __restrict__ Wout,
                           const float* __restrict__ gout, const float* __restrict__ bout,
                           const float* __restrict__ mout, const float* __restrict__ vout,
                           float* __restrict__ out) {
    __shared__ float sjs[SEH][16];
    int tid = threadIdx.x;
    int n0 = blockIdx.x * 16;
    int bb = n0 / HW;
    int hw0 = n0 % HW;

    int j = tid >> 4, nn = tid & 15;
    // gate for channel j (16 FMAs; g_p ready after se1)
    float hsum = 0.f;
#pragma unroll
    for (int jj = 0; jj < SEH; jj++)
        hsum += (g_p[bb * SEH + jj] * (1.f / HW)) * fc1[jj];
    float hid = fmaxf(hsum, 0.f);
    float gate = 1.f / (1.f + __expf(-(hid * fc2[j])));
    sjs[j][nn] = g_s[(size_t)bb * SEH * HW + (size_t)j * HW + hw0 + nn] * gate;
    __syncthreads();

    int o = tid;
    float wreg[SEH];
#pragma unroll
    for (int jj = 0; jj < SEH; jj++) wreg[jj] = Wout[o * SEH + jj];
    float scl = gout[o] * rsqrtf(vout[o] + EPS);
    float bo = bout[o] - mout[o] * scl;
    float* op = out + (size_t)bb * CO * HW + (size_t)o * HW + hw0;
#pragma unroll
    for (int nq = 0; nq < 4; nq++) {
        float4 a = make_float4(0.f, 0.f, 0.f, 0.f);
#pragma unroll
        for (int jj = 0; jj < SEH; jj++) {
            float wv = wreg[jj];
            a.x += wv * sjs[jj][nq * 4 + 0];
            a.y += wv * sjs[jj][nq * 4 + 1];
            a.z += wv * sjs[jj][nq * 4 + 2];
            a.w += wv * sjs[jj][nq * 4 + 3];
        }
        float4 r;
        r.x = a.x * scl + bo; r.y = a.y * scl + bo;
        r.z = a.z * scl + bo; r.w = a.w * scl + bo;
        *(float4*)&op[nq * 4] = r;
    }
}

// ---------------- launch ----------------
extern "C" void kernel_launch(void* const* d_in, const int* in_sizes, int n_in,
                              void* d_out, int out_size) {
    const float* x       = (const float*)d_in[0];
    const float* Wq      = (const float*)d_in[1];
    const float* Wk      = (const float*)d_in[2];
    const float* Wv      = (const float*)d_in[3];
    const float* rel_h   = (const float*)d_in[4];
    const float* rel_w   = (const float*)d_in[5];
    const float* agg_g1  = (const float*)d_in[6];
    const float* agg_b1  = (const float*)d_in[7];
    const float* agg_m1  = (const float*)d_in[8];
    const float* agg_v1  = (const float*)d_in[9];
    const float* agg_W   = (const float*)d_in[10];
    const float* agg_g2  = (const float*)d_in[11];
    const float* agg_b2  = (const float*)d_in[12];
    const float* agg_m2  = (const float*)d_in[13];
    const float* agg_v2  = (const float*)d_in[14];
    const float* se_Win  = (const float*)d_in[15];
    const float* se_g_in = (const float*)d_in[16];
    const float* se_b_in = (const float*)d_in[17];
    const float* se_m_in = (const float*)d_in[18];
    const float* se_v_in = (const float*)d_in[19];
    const float* se_fc1  = (const float*)d_in[20];
    const float* se_fc2  = (const float*)d_in[21];
    const float* se_Wout = (const float*)d_in[22];
    const float* se_g_out= (const float*)d_in[23];
    const float* se_b_out= (const float*)d_in[24];
    const float* se_m_out= (const float*)d_in[25];
    const float* se_v_out= (const float*)d_in[26];
    float* out = (float*)d_out;

    cudaFuncSetAttribute(attn_kernel,
                         cudaFuncAttributeMaxDynamicSharedMemorySize, SMEM_ATTN);

    prep_kernel<<<4160, 256>>>(x, Wq, Wk, Wv, agg_W);

    gemm_mma_kernel<<<dim3(98, 2, 3), 256>>>(nullptr, nullptr, nullptr, nullptr, 0);

    attn_kernel<<<dim3(196, NHEAD, NB), 256, SMEM_ATTN>>>(rel_h, rel_w,
                                                          agg_g1, agg_b1, agg_m1, agg_v1);

    gemm_mma_kernel<<<dim3(98, 2, 1), 256>>>(agg_g2, agg_b2, agg_m2, agg_v2, 1);

    se1_kernel<<<NPAN, 256>>>(se_Win, se_g_in, se_b_in, se_m_in, se_v_in);
    se3_kernel<<<NCOL / 16, 256>>>(se_fc1, se_fc2, se_Wout,
                                   se_g_out, se_b_out, se_m_out, se_v_out, out);
}

// round 16
// speedup vs baseline: 1.0345x; 1.0345x over previous
#include <cuda_runtime.h>
#include <math.h>
#include <stdint.h>

#define NB 4
#define CIN 256
#define CO 256
#define HDIM 56
#define WDIM 56
#define HW 3136
#define NCOL 12544     // NB*HW
#define NHEAD 2
#define HD 128
#define EPS 1e-5f
#define SEH 16
#define NPAN 98        // NCOL/128
#define CHUNKW 2048    // u32 per 128x16 chunk image

// attention dynamic smem layout (floats) — round-14 layout (51.3KB, 4 CTAs/SM)
#define KV_STRIDE 132
#define KV_ROWS 72
#define QB_OFF   (KV_ROWS * KV_STRIDE)          // 9504
#define AW_STRIDE 68
#define SS_OFF   (QB_OFF + 16 * KV_STRIDE)      // 11616
#define SS_STRIDE 76
#define SMEM_ATTN ((SS_OFF + 16 * SS_STRIDE) * 4)   // 51328 bytes

// ---------------- scratch (device globals, no allocation) ----------------
__device__ uint32_t g_Wp [4 * 2 * 16 * CHUNKW];   // weight A-panels (tf32 frag layout)
__device__ uint32_t g_xtp[NPAN * 16 * CHUNKW];    // x B-panels
__device__ uint32_t g_y1p[NPAN * 16 * CHUNKW];    // y1 B-panels
__device__ uint32_t g_y2p[NPAN * 16 * CHUNKW];    // y2 B-panels
__device__ float g_qt[NCOL * CO];   // [n][c]  (tf32-rounded)
__device__ float g_kt[NCOL * CO];
__device__ float g_vt[NCOL * CO];
__device__ float g_s [NB * SEH * HW]; // channel-major [b][j][hw]
__device__ float g_p [NB * SEH];

// ---------------- helpers ----------------
__device__ __forceinline__ uint32_t f2tf32(float f) {
    uint32_t u;
    asm("cvt.rna.tf32.f32 %0, %1;" : "=r"(u) : "f"(f));
    return u;
}
__device__ __forceinline__ float f2tf32f(float f) {
    return __uint_as_float(f2tf32(f));
}
__device__ __forceinline__ void cpasync16(uint32_t smem, const void* g) {
    asm volatile("cp.async.cg.shared.global [%0], [%1], 16;" :: "r"(smem), "l"(g));
}
__device__ __forceinline__ uint32_t smem_u32x(const void* p) {
    uint32_t a;
    asm("{ .reg .u64 t; cvta.to.shared.u64 t, %1; cvt.u32.u64 %0, t; }" : "=r"(a) : "l"(p));
    return a;
}
__device__ __forceinline__ void mma_tf32(float* d, const uint32_t* a, const uint32_t* b) {
    asm volatile(
        "mma.sync.aligned.m16n8k8.row.col.f32.tf32.tf32.f32 "
        "{%0,%1,%2,%3}, {%4,%5,%6,%7}, {%8,%9}, {%0,%1,%2,%3};"
        : "+f"(d[0]), "+f"(d[1]), "+f"(d[2]), "+f"(d[3])
        : "r"(a[0]), "r"(a[1]), "r"(a[2]), "r"(a[3]), "r"(b[0]), "r"(b[1]));
}

// A-image u32 offset within one 128x16 chunk (m rows x k cols)
__device__ __forceinline__ int a_off(int m, int k) {
    int ks = k >> 3, mtile = m >> 4, mi = m & 15;
    int lane = (mi & 7) * 4 + (k & 3);
    int slot = (mi >> 3) + 2 * ((k >> 2) & 1);
    int I = (ks * 8 + mtile) * 32 + lane;
    I ^= (I >> 3) & 3;
    return I * 4 + slot;
}
// B-image u32 offset within one 128x16 chunk (n rows x k cols)
__device__ __forceinline__ int b_off(int n, int k) {
    int ks = k >> 3, ntile = n >> 3;
    int lane = (n & 7) * 4 + (k & 3);
    int slot = (k >> 2) & 1;
    int I = (ks * 16 + ntile) * 32 + lane;
    I ^= (I >> 4) & 3;
    return I * 2 + slot;
}

// ---------------- prep: weight repack + x transpose (merged) ----------------
__global__ void prep_kernel(const float* __restrict__ x,
                            const float* __restrict__ Wq, const float* __restrict__ Wk,
                            const float* __restrict__ Wv, const float* __restrict__ Wa) {
    __shared__ float t[32][33];
    int tid = threadIdx.x;
    if (blockIdx.x < 1024) {
        if (blockIdx.x == 0 && tid < NB * SEH) g_p[tid] = 0.f;
        int v = blockIdx.x * 256 + tid;
        int mat = v >> 16;
        int rem = v & 65535;
        int o = rem >> 8, c = rem & 255;
        const float* W = (mat == 0) ? Wq : (mat == 1 ? Wk : (mat == 2 ? Wv : Wa));
        uint32_t u = f2tf32(W[o * 256 + c]);
        g_Wp[(((size_t)mat * 2 + (o >> 7)) * 16 + (c >> 4)) * CHUNKW + a_off(o & 127, c & 15)] = u;
    } else {
        int p = blockIdx.x - 1024;       // 3136 blocks = 4 * 8 * 98
        int b = p / 784;
        int r = p % 784;
        int c0 = (r / 98) * 32, p0 = (r % 98) * 32;
        int tx = tid & 31, ty = tid >> 5;
        const float* xb = x + ((size_t)b * CIN + c0) * HW + p0;
#pragma unroll
        for (int i = 0; i < 4; i++)
            t[ty * 4 + i][tx] = xb[(size_t)(ty * 4 + i) * HW + tx];
        __syncthreads();
        int c = c0 + tx;
#pragma unroll
        for (int i = 0; i < 4; i++) {
            int nglob = b * HW + p0 + ty * 4 + i;
            int ntile = nglob >> 7, nn = nglob & 127;
            g_xtp[((size_t)ntile * 16 + (c >> 4)) * CHUNKW + b_off(nn, c & 15)]
                = f2tf32(t[tx][ty * 4 + i]);
        }
    }
}

// ---------------- tensor-core tf32 GEMM, cp.async 3-stage, M128 x N128 -----
// mode 0: qkv (z selects matrix 0..2, B=g_xtp, out flat [n][c] tf32-rounded)
// mode 1: agg (matrix 3, B=g_y1p, out g_y2p panels with BN2, tf32-rounded)
__global__ __launch_bounds__(256, 2) void gemm_mma_kernel(
    const float* __restrict__ g2, const float* __restrict__ b2,
    const float* __restrict__ m2, const float* __restrict__ v2,
    int mode)
{
    __shared__ __align__(16) char smraw[49152];
    float* stg = (float*)smraw;

    int tid = threadIdx.x;
    int wid = tid >> 5, lane = tid & 31;
    int warpM = wid >> 2, warpN = wid & 3;
    int g = lane >> 2, t = lane & 3;

    int mat;
    const uint32_t* Bbase;
    float* outp = nullptr;
    if (mode == 0) {
        mat = blockIdx.z;
        Bbase = g_xtp;
        outp = (mat == 0) ? g_qt : (mat == 1 ? g_kt : g_vt);
    } else {
        mat = 3; Bbase = g_y1p;
    }
    int o0 = blockIdx.y * 128;
    int n0 = blockIdx.x * 128;

    const uint4* Apan = (const uint4*)&g_Wp[((size_t)mat * 2 + blockIdx.y) * 16 * CHUNKW];
    const uint4* Bpan = (const uint4*)&Bbase[(size_t)blockIdx.x * 16 * CHUNKW];
    uint32_t smb = smem_u32x(smraw);

    float acc[4][4][4];
#pragma unroll
    for (int i = 0; i < 4; i++)
#pragma unroll
        for (int j = 0; j < 4; j++)
#pragma unroll
            for (int s = 0; s < 4; s++) acc[i][j][s] = 0.f;

#define ISSUE(c, s) do { \
        uint32_t dst = smb + (s) * 16384; \
        const uint4* sa = Apan + (c) * 512; \
        const uint4* sb = Bpan + (c) * 512; \
        cpasync16(dst + tid * 16,                sa + tid); \
        cpasync16(dst + (tid + 256) * 16,        sa + tid + 256); \
        cpasync16(dst + 8192 + tid * 16,         sb + tid); \
        cpasync16(dst + 8192 + (tid + 256) * 16, sb + tid + 256); \
        asm volatile("cp.async.commit_group;"); \
    } while (0)

    ISSUE(0, 0);
    ISSUE(1, 1);

    for (int c = 0; c < 16; c++) {
        if (c < 15) asm volatile("cp.async.wait_group 1;");
        else        asm volatile("cp.async.wait_group 0;");
        __syncthreads();
        if (c + 2 < 16) ISSUE(c + 2, (c + 2) % 3);

        const uint4* Ab = (const uint4*)(smraw + (c % 3) * 16384);
        const uint2* Bb = (const uint2*)(smraw + (c % 3) * 16384 + 8192);
#pragma unroll
        for (int ks = 0; ks < 2; ks++) {
            uint32_t af[4][4], bf[4][2];
#pragma unroll
            for (int mt = 0; mt < 4; mt++) {
                int idx = (ks * 8 + warpM * 4 + mt) * 32 + lane;
                idx ^= (idx >> 3) & 3;
                uint4 v = Ab[idx];
                af[mt][0] = v.x; af[mt][1] = v.y; af[mt][2] = v.z; af[mt][3] = v.w;
            }
#pragma unroll
            for (int nt = 0; nt < 4; nt++) {
                int idx = (ks * 16 + warpN * 4 + nt) * 32 + lane;
                idx ^= (idx >> 4) & 3;
                uint2 v = Bb[idx];
                bf[nt][0] = v.x; bf[nt][1] = v.y;
            }
#pragma unroll
            for (int mt = 0; mt < 4; mt++)
#pragma unroll
                for (int nt = 0; nt < 4; nt++)
                    mma_tf32(acc[mt][nt], af[mt], bf[nt]);
        }
        __syncthreads();
    }
#undef ISSUE

    int h_of_warp = warpN >> 1;
    for (int h = 0; h < 2; h++) {
        __syncthreads();
        if (h_of_warp == h) {
#pragma unroll
            for (int mt = 0; mt < 4; mt++)
#pragma unroll
                for (int nt = 0; nt < 4; nt++)
#pragma unroll
                    for (int s = 0; s < 4; s++) {
                        int ol = warpM * 64 + mt * 16 + g + (s >> 1) * 8;
                        int nl = (warpN & 1) * 32 + nt * 8 + 2 * t + (s & 1);
                        stg[nl * 132 + ol] = acc[mt][nt][s];
                    }
        }
        __syncthreads();
#pragma unroll
        for (int i = 0; i < 8; i++) {
            int idx = tid + 256 * i;
            int nl = idx >> 5, o4 = idx & 31;
            float4 v = *(float4*)&stg[nl * 132 + o4 * 4];
            int nglob = n0 + h * 64 + nl;
            if (mode == 1) {
                int ob = o0 + o4 * 4;
                float4 gg = *(const float4*)&g2[ob];
                float4 bb = *(const float4*)&b2[ob];
                float4 mm = *(const float4*)&m2[ob];
                float4 vv = *(const float4*)&v2[ob];
                float s0 = gg.x * rsqrtf(vv.x + EPS);
                float s1 = gg.y * rsqrtf(vv.y + EPS);
                float s2 = gg.z * rsqrtf(vv.z + EPS);
                float s3 = gg.w * rsqrtf(vv.w + EPS);
                v.x = v.x * s0 + (bb.x - mm.x * s0);
                v.y = v.y * s1 + (bb.y - mm.y * s1);
                v.z = v.z * s2 + (bb.z - mm.z * s2);
                v.w = v.w * s3 + (bb.w - mm.w * s3);
                int pt = nglob >> 7, nn = nglob & 127;
                uint32_t* pb = &g_y2p[((size_t)pt * 16) * CHUNKW];
                const float* pv = &v.x;
#pragma unroll
                for (int j = 0; j < 4; j++) {
                    int ch = ob + j;
                    pb[(size_t)(ch >> 4) * CHUNKW + b_off(nn, ch & 15)] = f2tf32(pv[j]);
                }
            } else {
                v.x = f2tf32f(v.x); v.y = f2tf32f(v.y);
                v.z = f2tf32f(v.z); v.w = f2tf32f(v.w);
                *(float4*)&outp[(size_t)nglob * 256 + o0 + o4 * 4] = v;
            }
        }
    }
}

// ---------------- attention: tensor-core (mma.sync tf32), round-14 version --
// q/k/v already tf32-rounded in global; V serially overwrites the K buffer
// (51.3KB smem -> 4 CTAs/SM hides the latency across CTAs).
__global__ void attn_kernel(const float* __restrict__ rel_h,
                            const float* __restrict__ rel_w,
                            const float* __restrict__ g1, const float* __restrict__ b1,
                            const float* __restrict__ m1, const float* __restrict__ v1) {
    extern __shared__ float sm[];
    float* kv = sm;              // [72][132]  K' then V
    float* qb = sm + QB_OFF;     // [16][132]  Q, later attnw[16][68]
    float* sS = sm + SS_OFF;     // [16][76]   scores, later scl[128]/bo[128]

    int tid = threadIdx.x, wid = tid >> 5, lane = tid & 31;
    int g = lane >> 2, t4 = lane & 3;
    int tile = blockIdx.x;
    int th = tile / 14, tw = tile % 14;
    int nh = blockIdx.y, b = blockIdx.z;
    int h0 = th * 4, w0 = tw * 4;
    const float* rel = nh ? rel_w : rel_h;

    // ---- load Q (already tf32) ----
    const float* qbase = g_qt + (size_t)b * HW * CO + nh * HD;
#pragma unroll
    for (int i = 0; i < 2; i++) {
        int f = tid + 256 * i;
        int m = f >> 5, c4 = f & 31;
        int hw = (h0 + (m >> 2)) * WDIM + w0 + (m & 3);
        *(float4*)&qb[m * KV_STRIDE + c4 * 4] =
            *(const float4*)&qbase[(size_t)hw * CO + c4 * 4];
    }
    // ---- load K halo ----
    const float* kbase = g_kt + (size_t)b * HW * CO + nh * HD;
#pragma unroll
    for (int i = 0; i < 8; i++) {
        int f = tid + 256 * i;
        int pos = f >> 5, c4 = f & 31;
        int hh = h0 - 2 + (pos >> 3), ww = w0 - 2 + (pos & 7);
        float4 v = make_float4(0.f, 0.f, 0.f, 0.f);
        if ((unsigned)hh < HDIM && (unsigned)ww < WDIM)
            v = *(const float4*)&kbase[(size_t)(hh * WDIM + ww) * CO + c4 * 4];
        *(float4*)&kv[pos * KV_STRIDE + c4 * 4] = v;
    }
    // ---- rel rows 64..68, zeros 69..71 ----
    {
        int pos = 64 + (tid >> 5), c4 = tid & 31;
        float4 r = make_float4(0.f, 0.f, 0.f, 0.f);
        if (pos < 69) {
            int tp = pos - 64;
            r.x = f2tf32f(rel[(c4 * 4 + 0) * 5 + tp]);
            r.y = f2tf32f(rel[(c4 * 4 + 1) * 5 + tp]);
            r.z = f2tf32f(rel[(c4 * 4 + 2) * 5 + tp]);
            r.w = f2tf32f(rel[(c4 * 4 + 3) * 5 + tp]);
        }
        *(float4*)&kv[pos * KV_STRIDE + c4 * 4] = r;
    }
    __syncthreads();

    // ---- scores mma ----
    float accS0[4] = {0.f, 0.f, 0.f, 0.f};
    float accS1[4] = {0.f, 0.f, 0.f, 0.f};
#pragma unroll
    for (int ks = 0; ks < 16; ks++) {
        int kk = ks * 8 + t4;
        uint32_t a[4];
        a[0] = __float_as_uint(qb[g * KV_STRIDE + kk]);
        a[1] = __float_as_uint(qb[(g + 8) * KV_STRIDE + kk]);
        a[2] = __float_as_uint(qb[g * KV_STRIDE + kk + 4]);
        a[3] = __float_as_uint(qb[(g + 8) * KV_STRIDE + kk + 4]);
        uint32_t bb[2];
        bb[0] = __float_as_uint(kv[(wid * 8 + g) * KV_STRIDE + kk]);
        bb[1] = __float_as_uint(kv[(wid * 8 + g) * KV_STRIDE + kk + 4]);
        mma_tf32(accS0, a, bb);
        if (wid == 0) {
            uint32_t b2r[2];
            b2r[0] = __float_as_uint(kv[(64 + g) * KV_STRIDE + kk]);
            b2r[1] = __float_as_uint(kv[(64 + g) * KV_STRIDE + kk + 4]);
            mma_tf32(accS1, a, b2r);
        }
    }
#pragma unroll
    for (int s = 0; s < 4; s++) {
        int m = g + (s >> 1) * 8;
        sS[m * SS_STRIDE + wid * 8 + 2 * t4 + (s & 1)] = accS0[s];
        if (wid == 0) sS[m * SS_STRIDE + 64 + 2 * t4 + (s & 1)] = accS1[s];
    }
    __syncthreads();

    // ---- load V over kv rows 0..63 ----
    const float* vbase = g_vt + (size_t)b * HW * CO + nh * HD;
#pragma unroll
    for (int i = 0; i < 8; i++) {
        int f = tid + 256 * i;
        int pos = f >> 5, c4 = f & 31;
        int hh = h0 - 2 + (pos >> 3), ww = w0 - 2 + (pos & 7);
        float4 v = make_float4(0.f, 0.f, 0.f, 0.f);
        if ((unsigned)hh < HDIM && (unsigned)ww < WDIM)
            v = *(const float4*)&vbase[(size_t)(hh * WDIM + ww) * CO + c4 * 4];
        *(float4*)&kv[pos * KV_STRIDE + c4 * 4] = v;
    }

    // ---- softmax ----
#pragma unroll
    for (int pp = 0; pp < 2; pp++) {
        int pi = wid * 2 + pp;
        int py = pi >> 2, px = pi & 3;
        float scv = -1e30f;
        int pos = 0;
        if (lane < 25) {
            int ki = lane / 5, kj = lane % 5;
            pos = (py + ki) * 8 + (px + kj);
            float bias = sS[pi * SS_STRIDE + 64 + (nh ? kj : ki)];
            scv = (sS[pi * SS_STRIDE + pos] + bias) * 0.08838834764831845f;
        }
        float mx = scv;
#pragma unroll
        for (int m = 16; m; m >>= 1) mx = fmaxf(mx, __shfl_xor_sync(0xffffffffu, mx, m));
        float e = (lane < 25) ? __expf(scv - mx) : 0.f;
        float ssum = e;
#pragma unroll
        for (int m = 16; m; m >>= 1) ssum += __shfl_xor_sync(0xffffffffu, ssum, m);
        float wv = e / ssum;
        float* aw = qb;
        aw[pi * AW_STRIDE + lane] = 0.f;
        aw[pi * AW_STRIDE + 32 + lane] = 0.f;
        if (lane < 25) aw[pi * AW_STRIDE + pos] = f2tf32f(wv);
    }
    __syncthreads();

    // ---- BN1 scale/bias into sS ----
    if (tid < 128) {
        int ch = nh * HD + tid;
        float scl = g1[ch] * rsqrtf(v1[ch] + EPS);
        sS[tid] = scl;
        sS[128 + tid] = b1[ch] - m1[ch] * scl;
    }

    // ---- AV mma ----
    float accV0[4] = {0.f, 0.f, 0.f, 0.f};
    float accV1[4] = {0.f, 0.f, 0.f, 0.f};
#pragma unroll
    for (int ks = 0; ks < 8; ks++) {
        int kk = ks * 8 + t4;
        uint32_t a[4];
        a[0] = __float_as_uint(qb[g * AW_STRIDE + kk]);
        a[1] = __float_as_uint(qb[(g + 8) * AW_STRIDE + kk]);
        a[2] = __float_as_uint(qb[g * AW_STRIDE + kk + 4]);
        a[3] = __float_as_uint(qb[(g + 8) * AW_STRIDE + kk + 4]);
        uint32_t bb[2];
        int c0 = wid * 16 + g;
        bb[0] = __float_as_uint(kv[kk * KV_STRIDE + c0]);
        bb[1] = __float_as_uint(kv[(kk + 4) * KV_STRIDE + c0]);
        mma_tf32(accV0, a, bb);
        bb[0] = __float_as_uint(kv[kk * KV_STRIDE + c0 + 8]);
        bb[1] = __float_as_uint(kv[(kk + 4) * KV_STRIDE + c0 + 8]);
        mma_tf32(accV1, a, bb);
    }
    __syncthreads();

    // ---- epilogue: BN1 + relu -> g_y1p panels ----
#pragma unroll
    for (int j = 0; j < 2; j++) {
        const float* acc = j ? accV1 : accV0;
        int ntc = wid * 2 + j;
#pragma unroll
        for (int s = 0; s < 4; s++) {
            int m = g + (s >> 1) * 8;
            int c = ntc * 8 + 2 * t4 + (s & 1);
            int ch = nh * HD + c;
            int hw = (h0 + (m >> 2)) * WDIM + w0 + (m & 3);
            int nglob = b * HW + hw;
            float val = fmaxf(acc[s] * sS[c] + sS[128 + c], 0.f);
            g_y1p[((size_t)(nglob >> 7) * 16 + (ch >> 4)) * CHUNKW + b_off(nglob & 127, ch & 15)]
                = f2tf32(val);
        }
    }
}

// ---------------- SE stage 1: mma over y2 panels ----------------
__global__ __launch_bounds__(256) void se1_kernel(const float* __restrict__ Win,
                           const float* __restrict__ gin, const float* __restrict__ bin,
                           const float* __restrict__ min_, const float* __restrict__ vin) {
    __shared__ uint32_t Wf[4096];
    __shared__ float bnscl[SEH], bnbo[SEH];
    __shared__ float pool[2][SEH];
    int tid = threadIdx.x, wid = tid >> 5, lane = tid & 31;
    int g = lane >> 2, t4 = lane & 3;

#pragma unroll
    for (int it = 0; it < 16; it++) {
        int i = tid + 256 * it;
        int m = i >> 8, k = i & 255;
        int kc = k >> 4, ks = (k >> 3) & 1;
        int laneA = (m & 7) * 4 + (k & 3);
        int slot = (m >> 3) + 2 * ((k >> 2) & 1);
        Wf[((kc * 2 + ks) * 32 + laneA) * 4 + slot] = f2tf32(Win[m * 256 + k]);
    }
    if (tid < SEH) {
        float scl = gin[tid] * rsqrtf(vin[tid] + EPS);
        bnscl[tid] = scl;
        bnbo[tid] = bin[tid] - min_[tid] * scl;
        pool[0][tid] = 0.f;
        pool[1][tid] = 0.f;
    }
    __syncthreads();

    int panel = blockIdx.x;
    const uint32_t* Bpan = g_y2p + (size_t)panel * 16 * CHUNKW;

    float acc[2][4];
#pragma unroll
    for (int nt = 0; nt < 2; nt++)
#pragma unroll
        for (int s = 0; s < 4; s++) acc[nt][s] = 0.f;

#pragma unroll
    for (int kc = 0; kc < 16; kc++) {
#pragma unroll
        for (int ks = 0; ks < 2; ks++) {
            uint4 av = ((const uint4*)Wf)[(kc * 2 + ks) * 32 + lane];
            uint32_t a[4] = {av.x, av.y, av.z, av.w};
#pragma unroll
            for (int nt = 0; nt < 2; nt++) {
                int ntile = wid * 2 + nt;
                int idx = (ks * 16 + ntile) * 32 + lane;
                idx ^= (idx >> 4) & 3;
                uint2 bv = *(const uint2*)(Bpan + (size_t)kc * CHUNKW + idx * 2);
                uint32_t bb[2] = {bv.x, bv.y};
                mma_tf32(acc[nt], a, bb);
            }
        }
    }

    int b_first = (panel * 128) / HW;
#pragma unroll
    for (int nt = 0; nt < 2; nt++) {
        int ntile = wid * 2 + nt;
#pragma unroll
        for (int s = 0; s < 4; s++) {
            int j = g + (s >> 1) * 8;
            int pix = ntile * 8 + 2 * t4 + (s & 1);
            int nglob = panel * 128 + pix;
            int b = nglob / HW, hw = nglob % HW;
            float sv = fmaxf(acc[nt][s] * bnscl[j] + bnbo[j], 0.f);
            g_s[(size_t)b * SEH * HW + (size_t)j * HW + hw] = sv;
            atomicAdd(&pool[b - b_first][j], sv);
        }
    }
    __syncthreads();
    if (tid < 2 * SEH) {
        int bl = tid >> 4, j = tid & 15;
        int b = b_first + bl;
        if (b < NB) atomicAdd(&g_p[b * SEH + j], pool[bl][j]);
    }
}

// ---------------- SE stage 3 (gates computed inline from g_p) ----------------
__global__ void se3_kernel(const float* __restrict__ fc1, const float* __restrict__ fc2,
                           const float* __restrict__ Wout,
                           const float* __restrict__ gout, const float* __restrict__ bout,
                           const float* __restrict__ mout, const float* __restrict__ vout,
                           float* __restrict__ out) {
    __shared__ float sjs[SEH][16];
    int tid = threadIdx.x;
    int n0 = blockIdx.x * 16;
    int bb = n0 / HW;
    int hw0 = n0 % HW;

    int j = tid >> 4, nn = tid & 15;
    float hsum = 0.f;
#pragma unroll
    for (int jj = 0; jj < SEH; jj++)
        hsum += (g_p[bb * SEH + jj] * (1.f / HW)) * fc1[jj];
    float hid = fmaxf(hsum, 0.f);
    float gate = 1.f / (1.f + __expf(-(hid * fc2[j])));
    sjs[j][nn] = g_s[(size_t)bb * SEH * HW + (size_t)j * HW + hw0 + nn] * gate;
    __syncthreads();

    int o = tid;
    float wreg[SEH];
#pragma unroll
    for (int jj = 0; jj < SEH; jj++) wreg[jj] = Wout[o * SEH + jj];
    float scl = gout[o] * rsqrtf(vout[o] + EPS);
    float bo = bout[o] - mout[o] * scl;
    float* op = out + (size_t)bb * CO * HW + (size_t)o * HW + hw0;
#pragma unroll
    for (int nq = 0; nq < 4; nq++) {
        float4 a = make_float4(0.f, 0.f, 0.f, 0.f);
#pragma unroll
        for (int jj = 0; jj < SEH; jj++) {
            float wv = wreg[jj];
            a.x += wv * sjs[jj][nq * 4 + 0];
            a.y += wv * sjs[jj][nq * 4 + 1];
            a.z += wv * sjs[jj][nq * 4 + 2];
            a.w += wv * sjs[jj][nq * 4 + 3];
        }
        float4 r;
        r.x = a.x * scl + bo; r.y = a.y * scl + bo;
        r.z = a.z * scl + bo; r.w = a.w * scl + bo;
        *(float4*)&op[nq * 4] = r;
    }
}

// ---------------- launch ----------------
extern "C" void kernel_launch(void* const* d_in, const int* in_sizes, int n_in,
                              void* d_out, int out_size) {
    const float* x       = (const float*)d_in[0];
    const float* Wq      = (const float*)d_in[1];
    const float* Wk      = (const float*)d_in[2];
    const float* Wv      = (const float*)d_in[3];
    const float* rel_h   = (const float*)d_in[4];
    const float* rel_w   = (const float*)d_in[5];
    const float* agg_g1  = (const float*)d_in[6];
    const float* agg_b1  = (const float*)d_in[7];
    const float* agg_m1  = (const float*)d_in[8];
    const float* agg_v1  = (const float*)d_in[9];
    const float* agg_W   = (const float*)d_in[10];
    const float* agg_g2  = (const float*)d_in[11];
    const float* agg_b2  = (const float*)d_in[12];
    const float* agg_m2  = (const float*)d_in[13];
    const float* agg_v2  = (const float*)d_in[14];
    const float* se_Win  = (const float*)d_in[15];
    const float* se_g_in = (const float*)d_in[16];
    const float* se_b_in = (const float*)d_in[17];
    const float* se_m_in = (const float*)d_in[18];
    const float* se_v_in = (const float*)d_in[19];
    const float* se_fc1  = (const float*)d_in[20];
    const float* se_fc2  = (const float*)d_in[21];
    const float* se_Wout = (const float*)d_in[22];
    const float* se_g_out= (const float*)d_in[23];
    const float* se_b_out= (const float*)d_in[24];
    const float* se_m_out= (const float*)d_in[25];
    const float* se_v_out= (const float*)d_in[26];
    float* out = (float*)d_out;

    cudaFuncSetAttribute(attn_kernel,
                         cudaFuncAttributeMaxDynamicSharedMemorySize, SMEM_ATTN);

    prep_kernel<<<4160, 256>>>(x, Wq, Wk, Wv, agg_W);

    gemm_mma_kernel<<<dim3(98, 2, 3), 256>>>(nullptr, nullptr, nullptr, nullptr, 0);

    attn_kernel<<<dim3(196, NHEAD, NB), 256, SMEM_ATTN>>>(rel_h, rel_w,
                                                          agg_g1, agg_b1, agg_m1, agg_v1);

    gemm_mma_kernel<<<dim3(98, 2, 1), 256>>>(agg_g2, agg_b2, agg_m2, agg_v2, 1);

    se1_kernel<<<NPAN, 256>>>(se_Win, se_g_in, se_b_in, se_m_in, se_v_in);
    se3_kernel<<<NCOL / 16, 256>>>(se_fc1, se_fc2, se_Wout,
                                   se_g_out, se_b_out, se_m_out, se_v_out, out);
}